// round 14
// baseline (speedup 1.0000x reference)
#include <cuda_runtime.h>
#include <cstdint>

#define Bn 16
#define Nn 1024

// Scratch (device globals; no allocation allowed)
__device__ __align__(128) float g_S[Bn * Nn * 96];     // x@W0 + b0      [row][ec]
__device__ __align__(128) float g_sagg[Bn * Nn * 96];  // dis[m,e]*(x@W) [row][ec] == B[k'][c] flat
__device__ __align__(128) float g_dis[Bn * Nn * 3];    // deg^-1/2       [row][e]

#define FFMA2(d, a, b) \
    asm volatile("fma.rn.f32x2 %0, %1, %2, %0;" : "+l"(d) : "l"(a), "l"(b))
#define DUP2(d, a) \
    asm volatile("mov.b64 %0, {%1,%1};" : "=l"(d) : "f"(a))
#define UNPACK2(lo, hi, v) \
    asm volatile("mov.b64 {%0,%1}, %2;" : "=f"(lo), "=f"(hi) : "l"(v))
#define CPASYNC16(dst, src) \
    asm volatile("cp.async.cg.shared.global [%0], [%1], 16;" :: "r"(dst), "l"(src))
#define CP_COMMIT() asm volatile("cp.async.commit_group;" ::: "memory")
#define CP_WAIT1()  asm volatile("cp.async.wait_group 1;" ::: "memory")
#define CP_WAIT0()  asm volatile("cp.async.wait_group 0;" ::: "memory")

__device__ __forceinline__ uint32_t sptr(const void* p) {
    return (uint32_t)__cvta_generic_to_shared(p);
}

// ---------------------------------------------------------------------------
// Kernel 1 (fused): degrees + per-row linears.  One block (128 thr) per row.
// Consecutive-48B-per-thread e-phase trick keeps the sum divergence-free.
// ---------------------------------------------------------------------------
__global__ __launch_bounds__(128) void deg_kernel(
    const float* __restrict__ adj, const float* __restrict__ x,
    const float* __restrict__ W, const float* __restrict__ W0,
    const float* __restrict__ b0)
{
    int row = blockIdx.x;                    // b*N + n
    const float4* base = (const float4*)(adj + (size_t)row * 3072);
    int t = threadIdx.x;

    __shared__ float xsh[32];
    if (t < 32) xsh[t] = x[(size_t)row * 32 + t];

    float s0 = 0.f, s1 = 0.f, s2 = 0.f;
#pragma unroll
    for (int it = 0; it < 2; it++) {
        int q0 = 3 * (t + it * 128);         // q0 % 3 == 0 always
        float4 v0 = base[q0];
        float4 v1 = base[q0 + 1];
        float4 v2 = base[q0 + 2];
        s0 += v0.x + v0.w + v1.z + v2.y;
        s1 += v0.y + v1.x + v1.w + v2.z;
        s2 += v0.z + v1.y + v2.x + v2.w;
    }
#pragma unroll
    for (int off = 16; off; off >>= 1) {
        s0 += __shfl_down_sync(0xffffffffu, s0, off);
        s1 += __shfl_down_sync(0xffffffffu, s1, off);
        s2 += __shfl_down_sync(0xffffffffu, s2, off);
    }
    __shared__ float red[4][3];
    __shared__ float dis_s[3];
    int w = t >> 5, lane = t & 31;
    if (lane == 0) { red[w][0] = s0; red[w][1] = s1; red[w][2] = s2; }
    __syncthreads();
    if (t < 3) {
        float tot = red[0][t] + red[1][t] + red[2][t] + red[3][t];
        float d = rsqrtf(fmaxf(tot, 1.0f));
        dis_s[t] = d;
        g_dis[(size_t)row * 3 + t] = d;
    }
    __syncthreads();

    if (t < 96) {
        float a = 0.f, a0 = 0.f;
#pragma unroll
        for (int k = 0; k < 32; k++) {
            float xv = xsh[k];
            a  += xv * __ldg(W  + k * 96 + t);
            a0 += xv * __ldg(W0 + k * 96 + t);
        }
        g_sagg[(size_t)row * 96 + t] = dis_s[t >> 5] * a;
        g_S[(size_t)row * 96 + t]    = a0 + __ldg(b0 + t);
    }
}

// ---------------------------------------------------------------------------
// Kernel 2: aggregation SGEMM with e-PURE warps.
//   out[n][c] = mask * ( sum_e dis[n,e] * P_e[n][c] + sum_e S[n][ec] )
//   P_e[n][c] = sum_m adj[n][3m+e] * sagg_flat[(3m+e)*32 + c]
// Block = 192 thr (6 warps) = 64 n-rows; warp (we = w>>1, wh = w&1) handles
// only k' === we (mod 3) for its m-half -> accumulator is single-e, dis is
// applied at the MERGE (not in the mainloop).  Therefore:
//   - A is cp.async'd in natural [n][k'] layout (no transpose/staging/regs);
//     A-reads are LDS.32, row-pad 100 floats -> 8 rg-lanes on distinct banks
//     (1 phase each, cg-broadcast).
//   - Thread tile 8n x 8c (lane = rg*4+cg; n = rg+8i, c = cg*8..cg*8+7):
//     per m: 8 LDS.32 + 2 B-LDS.128 + 8 DUP2 + 32 FFMA2.
// m streamed in chunks of 32 (A 25KB + B 12KB, both double-buffered cp.async).
// 6 partials merged through smem with dis applied there.
// Merge slots: 64 floats/thread + 4 pad -> stride 68 (R13 bug: stride 36
// overran by 28 floats per thread and clobbered neighboring partials).
// ---------------------------------------------------------------------------
#define AS_ROW   100                        // floats per n-row (96 + 4 pad)
#define AS_FL    (64 * AS_ROW)              // 6400 floats per buffer
#define BS_FL    (96 * 32)                  // 3072 floats per buffer
#define SLOT_STR 68                         // merge slot stride (64 + 4 pad)
#define SMEM_TOT ((2 * AS_FL + 2 * BS_FL) * 4)   // 75776 B

__global__ __launch_bounds__(192, 2) void agg_kernel(
    const float* __restrict__ adj,
    const int* __restrict__ mask,
    float* __restrict__ out)
{
    extern __shared__ __align__(16) float sm[];
    float* As = sm;                          // [2][64][100]
    float* Bs = sm + 2 * AS_FL;              // [2][96*32]

    int t = threadIdx.x, w = t / 32, lane = t & 31;
    int we = w >> 1, wh = w & 1;             // edge type, m-half
    int rg = lane >> 2, cg = lane & 3;       // n-octet lane, c-octet
    int b = blockIdx.y, n0 = blockIdx.x * 64;

    const float* adjb = adj + ((size_t)b * Nn + n0) * 3072;
    const float* sgb  = g_sagg + (size_t)b * Nn * 96;
    uint32_t as_addr = sptr(As), bs_addr = sptr(Bs);

    // cp.async fills: A 1536 granules (8/thr), B 768 granules (4/thr)
    auto cpAB = [&](int buf, int ck) {
#pragma unroll
        for (int i = 0; i < 8; i++) {
            int q = t + 192 * i;
            int n = q / 24, seg = q % 24;
            CPASYNC16(as_addr + (uint32_t)(buf * AS_FL * 4 + n * (AS_ROW * 4) + seg * 16),
                      adjb + (size_t)n * 3072 + ck * 96 + seg * 4);
        }
#pragma unroll
        for (int i = 0; i < 4; i++) {
            int q = t + 192 * i;
            CPASYNC16(bs_addr + (uint32_t)(buf * BS_FL * 4 + q * 16),
                      sgb + (size_t)ck * 3072 + q * 4);
        }
        CP_COMMIT();
    };

    unsigned long long acc[8][4];            // [i: n=rg+8i][cpair]
#pragma unroll
    for (int i = 0; i < 8; i++)
#pragma unroll
        for (int p = 0; p < 4; p++) acc[i][p] = 0ull;

    cpAB(0, 0);
    cpAB(1, 1);

    for (int ck = 0; ck < 32; ck++) {
        if (ck < 31) { CP_WAIT1(); } else { CP_WAIT0(); }
        __syncthreads();                     // buffer ck ready for all

        const float* af = As + (ck & 1) * AS_FL + rg * AS_ROW;
        const float* bf = Bs + (ck & 1) * BS_FL + cg * 8;
#pragma unroll
        for (int j = 0; j < 16; j++) {
            const int ml = wh * 16 + j;      // m local to chunk
            const int kl = 3 * ml + we;      // k' local (e-pure)
            ulonglong2 bv0 = *(const ulonglong2*)(bf + kl * 32);
            ulonglong2 bv1 = *(const ulonglong2*)(bf + kl * 32 + 4);
#pragma unroll
            for (int i = 0; i < 8; i++) {
                float a = af[i * (8 * AS_ROW) + kl];
                unsigned long long a2;
                DUP2(a2, a);
                FFMA2(acc[i][0], a2, bv0.x);
                FFMA2(acc[i][1], a2, bv0.y);
                FFMA2(acc[i][2], a2, bv1.x);
                FFMA2(acc[i][3], a2, bv1.y);
            }
        }
        __syncthreads();                     // all reads of buffer ck done
        if (ck < 30) cpAB(ck & 1, ck + 2);
    }

    // ---- merge: 6 single-e partials, dis applied here ----
    float* slot = sm + (size_t)(w * 32 + lane) * SLOT_STR;   // 52 KB region
#pragma unroll
    for (int i = 0; i < 8; i++)
#pragma unroll
        for (int p = 0; p < 4; p++) {
            float lo, hi;
            UNPACK2(lo, hi, acc[i][p]);
            slot[(i * 4 + p) * 2]     = lo;
            slot[(i * 4 + p) * 2 + 1] = hi;
        }
    __syncthreads();

    for (int o = t; o < 1024; o += 192) {    // 64 n x 16 c-pairs
        int n = o >> 4, cp = o & 15;
        int rg2 = n & 7, i2 = n >> 3;
        int cg2 = cp >> 2, p2 = cp & 3;
        int foff = (i2 * 4 + p2) * 2;
        size_t rown = (size_t)b * Nn + n0 + n;
        float lo = 0.f, hi = 0.f;
#pragma unroll
        for (int e = 0; e < 3; e++) {
            float d = g_dis[rown * 3 + e];
            const float* p0 = sm + (size_t)((e * 2 + 0) * 32 + rg2 * 4 + cg2) * SLOT_STR + foff;
            const float* p1 = sm + (size_t)((e * 2 + 1) * 32 + rg2 * 4 + cg2) * SLOT_STR + foff;
            lo += d * (p0[0] + p1[0]);
            hi += d * (p0[1] + p1[1]);
        }
        const float* Sp = g_S + rown * 96 + cp * 2;
        lo += Sp[0] + Sp[32] + Sp[64];
        hi += Sp[1] + Sp[33] + Sp[65];
        if (mask[rown] == 0) { lo = 0.f; hi = 0.f; }
        float2 o2; o2.x = lo; o2.y = hi;
        *(float2*)(out + rown * 32 + cp * 2) = o2;
    }
}

// ---------------------------------------------------------------------------
extern "C" void kernel_launch(void* const* d_in, const int* in_sizes, int n_in,
                              void* d_out, int out_size)
{
    const float* x    = (const float*)d_in[0];   // [16,1024,32]
    const float* adj  = (const float*)d_in[1];   // [16,1024,1024,3]
    const int*   mask = (const int*)d_in[2];     // [16,1024] bool -> int32
    const float* W    = (const float*)d_in[3];   // [32,96]
    const float* W0   = (const float*)d_in[4];   // [32,96]
    const float* b0   = (const float*)d_in[5];   // [96]
    float*       out  = (float*)d_out;           // [16,1024,32]

    (void)in_sizes; (void)n_in; (void)out_size;

    cudaFuncSetAttribute(agg_kernel, cudaFuncAttributeMaxDynamicSharedMemorySize, SMEM_TOT);

    deg_kernel<<<Bn * Nn, 128>>>(adj, x, W, W0, b0);
    agg_kernel<<<dim3(Nn / 64, Bn), 192, SMEM_TOT>>>(adj, mask, out);
}